// round 4
// baseline (speedup 1.0000x reference)
#include <cuda_runtime.h>
#include <cstdint>

// Problem constants (from reference: B=1024, T=4096, N=2048, K=16, M=2^16)
#define T_DIM   4096
#define N_DIM   2048
#define K_DIM   16
#define THREADS 256
#define NPT     (N_DIM / THREADS)   // 8 neurons per thread (contiguous)

__global__ __launch_bounds__(THREADS)
void ram_layer_kernel(const int*  __restrict__ input_bits,   // [B, T]
                      const int*  __restrict__ connections,  // [N, K]
                      const int*  __restrict__ memory,       // [N, M]
                      float*      __restrict__ out)          // [B, N] float32 (0/1)
{
    __shared__ unsigned bits[T_DIM / 32];   // 4096-bit set, 512 B

    const int b   = blockIdx.x;
    const int tid = threadIdx.x;

    // ---- Pack this batch row's input bits into a shared bitset ----
    // p = j*256 + tid: lanes of a warp cover 32 consecutive positions, so
    // __ballot_sync yields exactly one bitset word.
    const int* row = input_bits + (size_t)b * T_DIM;
#pragma unroll
    for (int j = 0; j < T_DIM / THREADS; ++j) {
        int p = j * THREADS + tid;
        unsigned w = __ballot_sync(0xFFFFFFFFu, row[p] != 0);
        if ((tid & 31) == 0) bits[p >> 5] = w;
    }
    __syncthreads();

    // Each thread owns 8 CONTIGUOUS neurons: n0..n0+7
    const int n0 = tid * NPT;

    // ---- Build all 8 addresses (L2 connection reads + LDS bit tests) ----
    unsigned addr[NPT];
#pragma unroll
    for (int j = 0; j < NPT; ++j) {
        const int n = n0 + j;
        const int4* c4 = (const int4*)(connections + n * K_DIM);
        unsigned a = 0;
#pragma unroll
        for (int q = 0; q < 4; ++q) {
            int4 v = __ldg(&c4[q]);
            a |= ((bits[v.x >> 5] >> (v.x & 31)) & 1u) << (q * 4 + 0);
            a |= ((bits[v.y >> 5] >> (v.y & 31)) & 1u) << (q * 4 + 1);
            a |= ((bits[v.z >> 5] >> (v.z & 31)) & 1u) << (q * 4 + 2);
            a |= ((bits[v.w >> 5] >> (v.w & 31)) & 1u) << (q * 4 + 3);
        }
        addr[j] = a;
    }

    // ---- 8 independent random gathers, batched for MLP ----
    int vals[NPT];
#pragma unroll
    for (int j = 0; j < NPT; ++j) {
        const int n = n0 + j;
        vals[j] = __ldg(memory + (((size_t)n) << 16) + addr[j]);
    }

    // ---- float32 output (bool reference is compared as float), float4 stores ----
    float4* o4 = (float4*)(out + (size_t)b * N_DIM + n0);
    o4[0] = make_float4((float)(vals[0] & 1), (float)(vals[1] & 1),
                        (float)(vals[2] & 1), (float)(vals[3] & 1));
    o4[1] = make_float4((float)(vals[4] & 1), (float)(vals[5] & 1),
                        (float)(vals[6] & 1), (float)(vals[7] & 1));
}

extern "C" void kernel_launch(void* const* d_in, const int* in_sizes, int n_in,
                              void* d_out, int out_size) {
    // Identify inputs by their unique element counts (robust to metadata order):
    //   input_bits : B*T  = 4,194,304
    //   connections: N*K  = 32,768
    //   memory     : N*M  = 134,217,728
    const int* input_bits  = nullptr;
    const int* connections = nullptr;
    const int* memory      = nullptr;
    long long sz_bits = 0;

    for (int i = 0; i < n_in; ++i) {
        long long s = in_sizes[i];
        if (s == (long long)N_DIM * K_DIM) {
            connections = (const int*)d_in[i];
        } else if (s == (long long)N_DIM * 65536LL) {
            memory = (const int*)d_in[i];
        } else {
            input_bits = (const int*)d_in[i];
            sz_bits = s;
        }
    }

    const int B = (int)(sz_bits / T_DIM);   // 1024
    ram_layer_kernel<<<B, THREADS>>>(input_bits, connections, memory,
                                     (float*)d_out);
}

// round 5
// speedup vs baseline: 1.2703x; 1.2703x over previous
#include <cuda_runtime.h>
#include <cstdint>

// Problem constants (B=1024, T=4096, N=2048, K=16, M=2^16)
#define T_DIM   4096
#define N_DIM   2048
#define K_DIM   16
#define THREADS 256
#define NPT     (N_DIM / THREADS)   // 8 neurons per thread, strided by 256

// Transposed connections: conn_T[k][n] — coalesced per-warp reads.
__device__ int conn_T[K_DIM * N_DIM];

__global__ void transpose_conn_kernel(const int* __restrict__ conn) {
    int idx = blockIdx.x * blockDim.x + threadIdx.x;   // 0 .. N*K-1
    if (idx < N_DIM * K_DIM) {
        int n = idx >> 4;       // idx / K
        int k = idx & 15;       // idx % K
        conn_T[k * N_DIM + n] = conn[idx];
    }
}

__device__ __forceinline__ int ldcg_i32(const int* p) {
    int v;
    asm volatile("ld.global.cg.b32 %0, [%1];" : "=r"(v) : "l"(p));
    return v;
}

__global__ __launch_bounds__(THREADS)
void ram_layer_kernel(const int*  __restrict__ input_bits,   // [B, T]
                      const int*  __restrict__ memory,       // [N, M]
                      float*      __restrict__ out)          // [B, N] float32
{
    __shared__ unsigned bits[T_DIM / 32];   // 4096-bit set, 512 B

    const int b   = blockIdx.x;
    const int tid = threadIdx.x;

    // ---- Pack this batch row's bits into a shared bitset (coalesced+ballot) ----
    const int* row = input_bits + (size_t)b * T_DIM;
#pragma unroll
    for (int j = 0; j < T_DIM / THREADS; ++j) {
        int p = j * THREADS + tid;
        unsigned w = __ballot_sync(0xFFFFFFFFu, row[p] != 0);
        if ((tid & 31) == 0) bits[p >> 5] = w;
    }
    __syncthreads();

    // ---- Interleaved: build addr_j, immediately launch gather_j ----
    // Keeps up to 8 DRAM misses in flight while LDS/ALU work continues,
    // overlapping the L1-bound build phase with the DRAM-bound gather phase.
    int vals[NPT];
#pragma unroll
    for (int j = 0; j < NPT; ++j) {
        const int n = j * THREADS + tid;                 // neuron-per-lane: coalesced
        unsigned a = 0;
#pragma unroll
        for (int k = 0; k < K_DIM; ++k) {
            int c = __ldg(&conn_T[k * N_DIM + n]);       // 128B coalesced, L1-resident
            a |= ((bits[c >> 5] >> (c & 31)) & 1u) << k; // random LDS bit test
        }
        vals[j] = ldcg_i32(memory + (((size_t)n) << 16) + a);  // L2-only random gather
    }

    // ---- Coalesced float stores ----
#pragma unroll
    for (int j = 0; j < NPT; ++j) {
        out[(size_t)b * N_DIM + j * THREADS + tid] = (float)(vals[j] & 1);
    }
}

extern "C" void kernel_launch(void* const* d_in, const int* in_sizes, int n_in,
                              void* d_out, int out_size) {
    // Identify inputs by unique element counts (robust to metadata order):
    //   input_bits : B*T = 4,194,304   connections: N*K = 32,768
    //   memory     : N*M = 134,217,728
    const int* input_bits  = nullptr;
    const int* connections = nullptr;
    const int* memory      = nullptr;
    long long sz_bits = 0;

    for (int i = 0; i < n_in; ++i) {
        long long s = in_sizes[i];
        if (s == (long long)N_DIM * K_DIM) {
            connections = (const int*)d_in[i];
        } else if (s == (long long)N_DIM * 65536LL) {
            memory = (const int*)d_in[i];
        } else {
            input_bits = (const int*)d_in[i];
            sz_bits = s;
        }
    }

    const int B = (int)(sz_bits / T_DIM);   // 1024

    transpose_conn_kernel<<<(N_DIM * K_DIM + 255) / 256, 256>>>(connections);
    ram_layer_kernel<<<B, THREADS>>>(input_bits, memory, (float*)d_out);
}